// round 5
// baseline (speedup 1.0000x reference)
#include <cuda_runtime.h>
#include <stdint.h>
#include <math.h>

#define B_    2
#define T_    2048
#define H_    8
#define DK_   64
#define DIN_  512
#define DOUT_ 512
#define BH_   (B_ * H_)

// Scratch (__device__ globals per allocation-free rule)
__device__ float g_qh[BH_ * T_ * DK_];   // [bh][t][dk]
__device__ float g_kh[BH_ * T_ * DK_];
__device__ float g_vh[BH_ * T_ * DK_];
__device__ float g_oh[BH_ * T_ * DK_];   // attention output, head layout
__device__ float g_w[67108864];          // 256 MB [bh][q][k] = exp(scores)

// ---------------------------------------------------------------------------
// helpers
// ---------------------------------------------------------------------------
__device__ __forceinline__ uint32_t f2tf(float f) {
    uint32_t u;
    asm("cvt.rna.tf32.f32 %0, %1;" : "=r"(u) : "f"(f));
    return u;
}
__device__ __forceinline__ uint4 f2tf4(float4 v) {
    uint4 u;
    u.x = f2tf(v.x); u.y = f2tf(v.y); u.z = f2tf(v.z); u.w = f2tf(v.w);
    return u;
}
// 3xTF32 split: x = hi + lo (lo is the exact fp32 residual rounded to tf32)
__device__ __forceinline__ void split3(float x, uint32_t& hi, uint32_t& lo) {
    uint32_t h = f2tf(x);
    hi = h;
    lo = f2tf(x - __uint_as_float(h));
}
// D = A(16x8,row) * B(8x8,col) + D, tf32 operands, f32 accum
__device__ __forceinline__ void mma8(float c[4], const uint32_t a[4],
                                     uint32_t b0, uint32_t b1) {
    asm volatile(
        "mma.sync.aligned.m16n8k8.row.col.f32.tf32.tf32.f32 "
        "{%0,%1,%2,%3},{%4,%5,%6,%7},{%8,%9},{%0,%1,%2,%3};\n"
        : "+f"(c[0]), "+f"(c[1]), "+f"(c[2]), "+f"(c[3])
        : "r"(a[0]), "r"(a[1]), "r"(a[2]), "r"(a[3]), "r"(b0), "r"(b1));
}

#define PROJ_SMEM_BYTES ((128*36*2 + 64*36*2) * 4)       // 55296
#define ATTN_SMEM_BYTES ((192*68) * 4 + 128 * 4)         // 52224 + 512

// ---------------------------------------------------------------------------
// Kernel 1: fused QKV projection. Q/K use 3xTF32 (threshold-sensitive),
// V uses single tf32. Tile 128(M)x64(N), K-step 32, 256 threads.
// ---------------------------------------------------------------------------
__global__ __launch_bounds__(256, 2) void proj_kernel(
    const float* __restrict__ qx, const float* __restrict__ kx, const float* __restrict__ vx,
    const float* __restrict__ Wq, const float* __restrict__ bq,
    const float* __restrict__ Wk, const float* __restrict__ bk,
    const float* __restrict__ Wv, const float* __restrict__ bv)
{
    extern __shared__ uint32_t smp[];
    uint32_t* Xh = smp;                 // [128][36]
    uint32_t* Xl = Xh + 128 * 36;
    uint32_t* Wh = Xl + 128 * 36;       // [64][36]
    uint32_t* Wl = Wh + 64 * 36;

    const float *x, *W, *bias;
    float* out;
    if (blockIdx.z == 0)      { x = qx; W = Wq; bias = bq; out = g_qh; }
    else if (blockIdx.z == 1) { x = kx; W = Wk; bias = bk; out = g_kh; }
    else                      { x = vx; W = Wv; bias = bv; out = g_vh; }
    const bool precise = (blockIdx.z < 2);

    const int tid  = threadIdx.x;
    const int lane = tid & 31, w = tid >> 5;
    const int g = lane >> 2, t4 = lane & 3;
    const int m0 = blockIdx.y * 128;
    const int n0 = blockIdx.x * 64;

    float acc[8][4];
    #pragma unroll
    for (int i = 0; i < 8; i++)
        #pragma unroll
        for (int j = 0; j < 4; j++) acc[i][j] = 0.f;

    for (int k0 = 0; k0 < DIN_; k0 += 32) {
        __syncthreads();
        #pragma unroll
        for (int e = 0; e < 4; e++) {              // X tile 128x32
            int idx = e * 256 + tid;
            int r = idx >> 3, c4 = (idx & 7) * 4;
            float4 xv = *(const float4*)&x[(size_t)(m0 + r) * DIN_ + k0 + c4];
            uint4 h, l;
            split3(xv.x, h.x, l.x); split3(xv.y, h.y, l.y);
            split3(xv.z, h.z, l.z); split3(xv.w, h.w, l.w);
            *(uint4*)&Xh[r * 36 + c4] = h;
            *(uint4*)&Xl[r * 36 + c4] = l;
        }
        #pragma unroll
        for (int e = 0; e < 2; e++) {              // W tile 64x32
            int idx = e * 256 + tid;
            int r = idx >> 3, c4 = (idx & 7) * 4;
            float4 wv = *(const float4*)&W[(size_t)(n0 + r) * DIN_ + k0 + c4];
            uint4 h, l;
            split3(wv.x, h.x, l.x); split3(wv.y, h.y, l.y);
            split3(wv.z, h.z, l.z); split3(wv.w, h.w, l.w);
            *(uint4*)&Wh[r * 36 + c4] = h;
            *(uint4*)&Wl[r * 36 + c4] = l;
        }
        __syncthreads();

        uint32_t ah[4][4], al[4][4];
        const int r0 = (16 * w + g) * 36, r1 = r0 + 8 * 36;
        #pragma unroll
        for (int kc = 0; kc < 4; kc++) {
            ah[kc][0] = Xh[r0 + kc * 8 + t4];
            ah[kc][1] = Xh[r1 + kc * 8 + t4];
            ah[kc][2] = Xh[r0 + kc * 8 + t4 + 4];
            ah[kc][3] = Xh[r1 + kc * 8 + t4 + 4];
            al[kc][0] = Xl[r0 + kc * 8 + t4];
            al[kc][1] = Xl[r1 + kc * 8 + t4];
            al[kc][2] = Xl[r0 + kc * 8 + t4 + 4];
            al[kc][3] = Xl[r1 + kc * 8 + t4 + 4];
        }
        #pragma unroll
        for (int nc = 0; nc < 8; nc++) {
            const int br = (nc * 8 + g) * 36;
            #pragma unroll
            for (int kc = 0; kc < 4; kc++) {
                uint32_t b0h = Wh[br + kc * 8 + t4];
                uint32_t b1h = Wh[br + kc * 8 + t4 + 4];
                mma8(acc[nc], ah[kc], b0h, b1h);
                if (precise) {
                    uint32_t b0l = Wl[br + kc * 8 + t4];
                    uint32_t b1l = Wl[br + kc * 8 + t4 + 4];
                    mma8(acc[nc], ah[kc], b0l, b1l);   // hi*lo
                    mma8(acc[nc], al[kc], b0h, b1h);   // lo*hi
                }
            }
        }
    }

    const int h = n0 >> 6;
    const int mA = m0 + 16 * w + g;
    const int bA = mA >> 11, tA = mA & (T_ - 1);
    const int mBr = mA + 8;
    const int bB = mBr >> 11, tB = mBr & (T_ - 1);
    float* rowA = out + ((size_t)(bA * H_ + h) * T_ + tA) * DK_;
    float* rowB = out + ((size_t)(bB * H_ + h) * T_ + tB) * DK_;
    #pragma unroll
    for (int nc = 0; nc < 8; nc++) {
        int col = nc * 8 + 2 * t4;
        float bx = bias[n0 + col], by = bias[n0 + col + 1];
        *(float2*)&rowA[col] = make_float2(acc[nc][0] + bx, acc[nc][1] + by);
        *(float2*)&rowB[col] = make_float2(acc[nc][2] + bx, acc[nc][3] + by);
    }
}

// ---------------------------------------------------------------------------
// Kernel 2: attention. Pass 1: QK^T in 3xTF32, w=exp(S) streamed to g_w,
// row sums Z accumulated (single QK computation). Pass 2: reload w, threshold
// against exact fp32 Z/T, PV in tf32, scale 1/Z.
// Block = (bh, 128 q-rows), 256 threads, key tile 64.
// ---------------------------------------------------------------------------
__global__ __launch_bounds__(256, 1) void attn_kernel()
{
    extern __shared__ uint32_t sma[];
    // pass1: Qf[128][68] staging (aliases Kh+Kl); Kh[64][68]; Kl[64][68]
    // pass2: Ps[128][68] (aliases Kh+Kl); Vs[64][68]
    float*    Qf = (float*)sma;
    uint32_t* Kh = sma;
    uint32_t* Kl = Kh + 64 * 68;
    uint32_t* Ps = sma;
    uint32_t* Vs = sma + 128 * 68;
    float*    thr_s = (float*)(sma + 192 * 68);   // [128]

    const int bh = blockIdx.x;
    const int q0 = blockIdx.y * 128;
    const float* qh = g_qh + (size_t)bh * T_ * DK_;
    const float* kh = g_kh + (size_t)bh * T_ * DK_;
    const float* vh = g_vh + (size_t)bh * T_ * DK_;
    float* wb = g_w + (size_t)bh * T_ * T_;
    float* oh = g_oh + (size_t)bh * T_ * DK_;

    const int tid  = threadIdx.x;
    const int lane = tid & 31, w = tid >> 5;
    const int g = lane >> 2, t4 = lane & 3;

    // ---- stage raw Q tile, extract hi/lo A-fragments ----
    #pragma unroll
    for (int e = 0; e < 8; e++) {
        int idx = e * 256 + tid;
        int r = idx >> 4, c4 = (idx & 15) * 4;
        *(float4*)&Qf[r * 68 + c4] = *(const float4*)&qh[(size_t)(q0 + r) * DK_ + c4];
    }
    __syncthreads();
    uint32_t qh_[8][4], ql_[8][4];
    {
        const int r0 = (16 * w + g) * 68, r1 = r0 + 8 * 68;
        #pragma unroll
        for (int kc = 0; kc < 8; kc++) {
            split3(Qf[r0 + kc * 8 + t4],     qh_[kc][0], ql_[kc][0]);
            split3(Qf[r1 + kc * 8 + t4],     qh_[kc][1], ql_[kc][1]);
            split3(Qf[r0 + kc * 8 + t4 + 4], qh_[kc][2], ql_[kc][2]);
            split3(Qf[r1 + kc * 8 + t4 + 4], qh_[kc][3], ql_[kc][3]);
        }
    }

    // ---- pass 1: S in 3xTF32, stream w=exp(S) to g_w, accumulate Z ----
    float z0 = 0.f, z1 = 0.f;
    float* wrA = wb + (size_t)(q0 + 16 * w + g) * T_;
    float* wrB = wrA + 8 * T_;
    for (int kt = 0; kt < T_ / 64; kt++) {
        const int j0 = kt * 64;
        __syncthreads();
        #pragma unroll
        for (int e = 0; e < 4; e++) {
            int idx = e * 256 + tid;
            int r = idx >> 4, c4 = (idx & 15) * 4;
            float4 kv = *(const float4*)&kh[(size_t)(j0 + r) * DK_ + c4];
            uint4 h, l;
            split3(kv.x, h.x, l.x); split3(kv.y, h.y, l.y);
            split3(kv.z, h.z, l.z); split3(kv.w, h.w, l.w);
            *(uint4*)&Kh[r * 68 + c4] = h;
            *(uint4*)&Kl[r * 68 + c4] = l;
        }
        __syncthreads();
        #pragma unroll
        for (int kc = 0; kc < 8; kc++) {
            float c[4] = {0.f, 0.f, 0.f, 0.f};
            const int br = (kc * 8 + g) * 68;
            #pragma unroll
            for (int dc = 0; dc < 8; dc++) {
                uint32_t b0h = Kh[br + dc * 8 + t4];
                uint32_t b1h = Kh[br + dc * 8 + t4 + 4];
                uint32_t b0l = Kl[br + dc * 8 + t4];
                uint32_t b1l = Kl[br + dc * 8 + t4 + 4];
                mma8(c, qh_[dc], b0h, b1h);
                mma8(c, qh_[dc], b0l, b1l);
                mma8(c, ql_[dc], b0h, b1h);
            }
            float w0 = __expf(c[0]);
            float w1 = __expf(c[1]);
            float w2 = __expf(c[2]);
            float w3 = __expf(c[3]);
            z0 += w0 + w1;
            z1 += w2 + w3;
            const int col = j0 + kc * 8 + 2 * t4;
            *(float2*)&wrA[col] = make_float2(w0, w1);
            *(float2*)&wrB[col] = make_float2(w2, w3);
        }
    }
    z0 += __shfl_xor_sync(0xffffffffu, z0, 1);
    z0 += __shfl_xor_sync(0xffffffffu, z0, 2);
    z1 += __shfl_xor_sync(0xffffffffu, z1, 1);
    z1 += __shfl_xor_sync(0xffffffffu, z1, 2);
    const float inv0 = 1.0f / z0, inv1 = 1.0f / z1;
    if (t4 == 0) {
        thr_s[16 * w + g]     = z0 * (1.0f / (float)T_);
        thr_s[16 * w + g + 8] = z1 * (1.0f / (float)T_);
    }

    // ---- pass 2: reload w, threshold (exact fp32), PV ----
    float o[8][4];
    #pragma unroll
    for (int i = 0; i < 8; i++)
        #pragma unroll
        for (int j = 0; j < 4; j++) o[i][j] = 0.f;

    const int r0p = (16 * w + g) * 68, r1p = r0p + 8 * 68;
    for (int kt = 0; kt < T_ / 64; kt++) {
        const int j0 = kt * 64;
        __syncthreads();   // orders thr_s writes (first iter) + Ps/Vs reuse
        #pragma unroll
        for (int e = 0; e < 8; e++) {              // P tile 128x64: load, thresh, cvt
            int idx = e * 256 + tid;
            int r = idx >> 4, j4 = (idx & 15) * 4;
            float4 w4 = *(const float4*)&wb[(size_t)(q0 + r) * T_ + j0 + j4];
            float th = thr_s[r];
            uint4 p;
            p.x = f2tf(w4.x > th ? w4.x : 0.f);
            p.y = f2tf(w4.y > th ? w4.y : 0.f);
            p.z = f2tf(w4.z > th ? w4.z : 0.f);
            p.w = f2tf(w4.w > th ? w4.w : 0.f);
            *(uint4*)&Ps[r * 68 + j4] = p;
        }
        #pragma unroll
        for (int e = 0; e < 4; e++) {              // V tile 64x64
            int idx = e * 256 + tid;
            int r = idx >> 4, d4 = (idx & 15) * 4;
            float4 vv = *(const float4*)&vh[(size_t)(j0 + r) * DK_ + d4];
            *(uint4*)&Vs[r * 68 + d4] = f2tf4(vv);
        }
        __syncthreads();
        #pragma unroll
        for (int kc = 0; kc < 8; kc++) {
            uint32_t pa[4];
            pa[0] = Ps[r0p + kc * 8 + t4];
            pa[1] = Ps[r1p + kc * 8 + t4];
            pa[2] = Ps[r0p + kc * 8 + t4 + 4];
            pa[3] = Ps[r1p + kc * 8 + t4 + 4];
            const int vr0 = (kc * 8 + t4) * 68;
            const int vr1 = vr0 + 4 * 68;
            #pragma unroll
            for (int dn = 0; dn < 8; dn++) {
                uint32_t b0 = Vs[vr0 + dn * 8 + g];
                uint32_t b1 = Vs[vr1 + dn * 8 + g];
                mma8(o[dn], pa, b0, b1);
            }
        }
    }

    float* rowA = oh + (size_t)(q0 + 16 * w + g) * DK_;
    float* rowB = rowA + 8 * DK_;
    #pragma unroll
    for (int dn = 0; dn < 8; dn++) {
        int col = dn * 8 + 2 * t4;
        *(float2*)&rowA[col] = make_float2(o[dn][0] * inv0, o[dn][1] * inv0);
        *(float2*)&rowB[col] = make_float2(o[dn][2] * inv1, o[dn][3] * inv1);
    }
}

// ---------------------------------------------------------------------------
// Kernel 3: output projection (single tf32, smooth path).
// ---------------------------------------------------------------------------
__global__ __launch_bounds__(256, 2) void outproj_kernel(
    const float* __restrict__ Wo, const float* __restrict__ bo,
    float* __restrict__ out)
{
    __shared__ uint32_t Xs[128 * 36];
    __shared__ uint32_t Ws[64 * 36];

    const int tid  = threadIdx.x;
    const int lane = tid & 31, w = tid >> 5;
    const int g = lane >> 2, t4 = lane & 3;
    const int m0 = blockIdx.y * 128;
    const int n0 = blockIdx.x * 64;

    float acc[8][4];
    #pragma unroll
    for (int i = 0; i < 8; i++)
        #pragma unroll
        for (int j = 0; j < 4; j++) acc[i][j] = 0.f;

    for (int k0 = 0; k0 < DOUT_; k0 += 32) {
        __syncthreads();
        #pragma unroll
        for (int e = 0; e < 4; e++) {
            int idx = e * 256 + tid;
            int r = idx >> 3, c4 = (idx & 7) * 4;
            int m = m0 + r, bb = m >> 11, t = m & (T_ - 1);
            int kg = k0 + c4, h = kg >> 6, dk = kg & 63;
            float4 xv = *(const float4*)&g_oh[((size_t)(bb * H_ + h) * T_ + t) * DK_ + dk];
            *(uint4*)&Xs[r * 36 + c4] = f2tf4(xv);
        }
        #pragma unroll
        for (int e = 0; e < 2; e++) {
            int idx = e * 256 + tid;
            int r = idx >> 3, c4 = (idx & 7) * 4;
            float4 wv = *(const float4*)&Wo[(size_t)(n0 + r) * DOUT_ + k0 + c4];
            *(uint4*)&Ws[r * 36 + c4] = f2tf4(wv);
        }
        __syncthreads();

        uint32_t a[4][4];
        const int r0 = (16 * w + g) * 36, r1 = r0 + 8 * 36;
        #pragma unroll
        for (int kc = 0; kc < 4; kc++) {
            a[kc][0] = Xs[r0 + kc * 8 + t4];
            a[kc][1] = Xs[r1 + kc * 8 + t4];
            a[kc][2] = Xs[r0 + kc * 8 + t4 + 4];
            a[kc][3] = Xs[r1 + kc * 8 + t4 + 4];
        }
        #pragma unroll
        for (int nc = 0; nc < 8; nc++) {
            const int br = (nc * 8 + g) * 36;
            #pragma unroll
            for (int kc = 0; kc < 4; kc++) {
                uint32_t b0 = Ws[br + kc * 8 + t4];
                uint32_t b1 = Ws[br + kc * 8 + t4 + 4];
                mma8(acc[nc], a[kc], b0, b1);
            }
        }
    }

    const int mA = m0 + 16 * w + g;
    float* rowA = out + (size_t)mA * DIN_ + n0;
    float* rowB = rowA + 8 * DIN_;
    #pragma unroll
    for (int nc = 0; nc < 8; nc++) {
        int col = nc * 8 + 2 * t4;
        float bx = bo[n0 + col], by = bo[n0 + col + 1];
        *(float2*)&rowA[col] = make_float2(acc[nc][0] + bx, acc[nc][1] + by);
        *(float2*)&rowB[col] = make_float2(acc[nc][2] + bx, acc[nc][3] + by);
    }
}

// ---------------------------------------------------------------------------
extern "C" void kernel_launch(void* const* d_in, const int* in_sizes, int n_in,
                              void* d_out, int out_size)
{
    const float* q  = (const float*)d_in[0];
    const float* k  = (const float*)d_in[1];
    const float* v  = (const float*)d_in[2];
    const float* Wq = (const float*)d_in[3];
    const float* bq = (const float*)d_in[4];
    const float* Wk = (const float*)d_in[5];
    const float* bk = (const float*)d_in[6];
    const float* Wv = (const float*)d_in[7];
    const float* bv = (const float*)d_in[8];
    const float* Wo = (const float*)d_in[9];
    const float* bo = (const float*)d_in[10];
    float* out = (float*)d_out;

    // Unconditional (idempotent, graph-capture-safe; no static state).
    cudaFuncSetAttribute(proj_kernel,
        cudaFuncAttributeMaxDynamicSharedMemorySize, PROJ_SMEM_BYTES);
    cudaFuncSetAttribute(attn_kernel,
        cudaFuncAttributeMaxDynamicSharedMemorySize, ATTN_SMEM_BYTES);

    proj_kernel<<<dim3(DOUT_ / 64, (B_ * T_) / 128, 3), 256, PROJ_SMEM_BYTES>>>(
        q, k, v, Wq, bq, Wk, bk, Wv, bv);

    attn_kernel<<<dim3(BH_, T_ / 128), 256, ATTN_SMEM_BYTES>>>();

    outproj_kernel<<<dim3(DIN_ / 64, (B_ * T_) / 128), 256>>>(Wo, bo, out);
}

// round 6
// speedup vs baseline: 1.2202x; 1.2202x over previous
#include <cuda_runtime.h>
#include <stdint.h>
#include <math.h>

#define B_    2
#define T_    2048
#define H_    8
#define DK_   64
#define DIN_  512
#define DOUT_ 512
#define BH_   (B_ * H_)

// Scratch (__device__ globals per allocation-free rule)
__device__ float g_qh[BH_ * T_ * DK_];   // [bh][t][dk]
__device__ float g_kh[BH_ * T_ * DK_];
__device__ float g_vh[BH_ * T_ * DK_];
__device__ float g_oh[BH_ * T_ * DK_];   // attention output, head layout
__device__ float g_w[67108864];          // 256 MB [bh][q][k] = exp(scores)

// ---------------------------------------------------------------------------
// helpers
// ---------------------------------------------------------------------------
__device__ __forceinline__ uint32_t f2tf(float f) {
    uint32_t u;
    asm("cvt.rna.tf32.f32 %0, %1;" : "=r"(u) : "f"(f));
    return u;
}
__device__ __forceinline__ uint4 f2tf4(float4 v) {
    uint4 u;
    u.x = f2tf(v.x); u.y = f2tf(v.y); u.z = f2tf(v.z); u.w = f2tf(v.w);
    return u;
}
// 3xTF32 split: x = hi + lo (lo is the exact fp32 residual rounded to tf32)
__device__ __forceinline__ void split3(float x, uint32_t& hi, uint32_t& lo) {
    uint32_t h = f2tf(x);
    hi = h;
    lo = f2tf(x - __uint_as_float(h));
}
// D = A(16x8,row) * B(8x8,col) + D, tf32 operands, f32 accum
__device__ __forceinline__ void mma8(float c[4], const uint32_t a[4],
                                     uint32_t b0, uint32_t b1) {
    asm volatile(
        "mma.sync.aligned.m16n8k8.row.col.f32.tf32.tf32.f32 "
        "{%0,%1,%2,%3},{%4,%5,%6,%7},{%8,%9},{%0,%1,%2,%3};\n"
        : "+f"(c[0]), "+f"(c[1]), "+f"(c[2]), "+f"(c[3])
        : "r"(a[0]), "r"(a[1]), "r"(a[2]), "r"(a[3]), "r"(b0), "r"(b1));
}

#define PROJ_SMEM_BYTES ((128*36*2 + 64*36*2) * 4)       // 55296
// attn smem: Kh[64][68] | Kl[64][68] | Qlo[128][68] | thr[128]
// pass2 aliases: Ps[128][68] over Kh+Kl, Vs[64][68] over Qlo
#define ATTN_SMEM_BYTES ((256*68 + 128) * 4)             // 70144

// ---------------------------------------------------------------------------
// Kernel 1: fused QKV projection. Q/K use 3xTF32, V single tf32.
// Tile 128(M)x64(N), K-step 32, 256 threads. ILP: kc-outer, 3 nc-sweeps.
// ---------------------------------------------------------------------------
__global__ __launch_bounds__(256, 2) void proj_kernel(
    const float* __restrict__ qx, const float* __restrict__ kx, const float* __restrict__ vx,
    const float* __restrict__ Wq, const float* __restrict__ bq,
    const float* __restrict__ Wk, const float* __restrict__ bk,
    const float* __restrict__ Wv, const float* __restrict__ bv)
{
    extern __shared__ uint32_t smp[];
    uint32_t* Xh = smp;                 // [128][36]
    uint32_t* Xl = Xh + 128 * 36;
    uint32_t* Wh = Xl + 128 * 36;       // [64][36]
    uint32_t* Wl = Wh + 64 * 36;

    const float *x, *W, *bias;
    float* out;
    if (blockIdx.z == 0)      { x = qx; W = Wq; bias = bq; out = g_qh; }
    else if (blockIdx.z == 1) { x = kx; W = Wk; bias = bk; out = g_kh; }
    else                      { x = vx; W = Wv; bias = bv; out = g_vh; }
    const bool precise = (blockIdx.z < 2);

    const int tid  = threadIdx.x;
    const int lane = tid & 31, w = tid >> 5;
    const int g = lane >> 2, t4 = lane & 3;
    const int m0 = blockIdx.y * 128;
    const int n0 = blockIdx.x * 64;

    float acc[8][4];
    #pragma unroll
    for (int i = 0; i < 8; i++)
        #pragma unroll
        for (int j = 0; j < 4; j++) acc[i][j] = 0.f;

    for (int k0 = 0; k0 < DIN_; k0 += 32) {
        __syncthreads();
        #pragma unroll
        for (int e = 0; e < 4; e++) {              // X tile 128x32
            int idx = e * 256 + tid;
            int r = idx >> 3, c4 = (idx & 7) * 4;
            float4 xv = *(const float4*)&x[(size_t)(m0 + r) * DIN_ + k0 + c4];
            uint4 h, l;
            split3(xv.x, h.x, l.x); split3(xv.y, h.y, l.y);
            split3(xv.z, h.z, l.z); split3(xv.w, h.w, l.w);
            *(uint4*)&Xh[r * 36 + c4] = h;
            *(uint4*)&Xl[r * 36 + c4] = l;
        }
        #pragma unroll
        for (int e = 0; e < 2; e++) {              // W tile 64x32
            int idx = e * 256 + tid;
            int r = idx >> 3, c4 = (idx & 7) * 4;
            float4 wv = *(const float4*)&W[(size_t)(n0 + r) * DIN_ + k0 + c4];
            uint4 h, l;
            split3(wv.x, h.x, l.x); split3(wv.y, h.y, l.y);
            split3(wv.z, h.z, l.z); split3(wv.w, h.w, l.w);
            *(uint4*)&Wh[r * 36 + c4] = h;
            *(uint4*)&Wl[r * 36 + c4] = l;
        }
        __syncthreads();

        uint32_t ah[4][4], al[4][4];
        const int r0 = (16 * w + g) * 36, r1 = r0 + 8 * 36;
        #pragma unroll
        for (int kc = 0; kc < 4; kc++) {
            ah[kc][0] = Xh[r0 + kc * 8 + t4];
            ah[kc][1] = Xh[r1 + kc * 8 + t4];
            ah[kc][2] = Xh[r0 + kc * 8 + t4 + 4];
            ah[kc][3] = Xh[r1 + kc * 8 + t4 + 4];
            al[kc][0] = Xl[r0 + kc * 8 + t4];
            al[kc][1] = Xl[r1 + kc * 8 + t4];
            al[kc][2] = Xl[r0 + kc * 8 + t4 + 4];
            al[kc][3] = Xl[r1 + kc * 8 + t4 + 4];
        }
        // kc outer; per kc: 3 sweeps over nc (hh, hl, lh). Accumulation order
        // into acc[nc] per kc is hh,hl,lh — identical to the nc-outer version.
        #pragma unroll
        for (int kc = 0; kc < 4; kc++) {
            uint32_t bh0[8], bh1[8];
            #pragma unroll
            for (int nc = 0; nc < 8; nc++) {
                const int br = (nc * 8 + g) * 36 + kc * 8;
                bh0[nc] = Wh[br + t4];
                bh1[nc] = Wh[br + t4 + 4];
                mma8(acc[nc], ah[kc], bh0[nc], bh1[nc]);
            }
            if (precise) {
                #pragma unroll
                for (int nc = 0; nc < 8; nc++) {
                    const int br = (nc * 8 + g) * 36 + kc * 8;
                    uint32_t bl0 = Wl[br + t4];
                    uint32_t bl1 = Wl[br + t4 + 4];
                    mma8(acc[nc], ah[kc], bl0, bl1);   // hi*lo
                }
                #pragma unroll
                for (int nc = 0; nc < 8; nc++)
                    mma8(acc[nc], al[kc], bh0[nc], bh1[nc]);   // lo*hi
            }
        }
    }

    const int h = n0 >> 6;
    const int mA = m0 + 16 * w + g;
    const int bA = mA >> 11, tA = mA & (T_ - 1);
    const int mBr = mA + 8;
    const int bB = mBr >> 11, tB = mBr & (T_ - 1);
    float* rowA = out + ((size_t)(bA * H_ + h) * T_ + tA) * DK_;
    float* rowB = out + ((size_t)(bB * H_ + h) * T_ + tB) * DK_;
    #pragma unroll
    for (int nc = 0; nc < 8; nc++) {
        int col = nc * 8 + 2 * t4;
        float bx = bias[n0 + col], by = bias[n0 + col + 1];
        *(float2*)&rowA[col] = make_float2(acc[nc][0] + bx, acc[nc][1] + by);
        *(float2*)&rowB[col] = make_float2(acc[nc][2] + bx, acc[nc][3] + by);
    }
}

// ---------------------------------------------------------------------------
// Kernel 2: attention. Pass 1: QK^T in 3xTF32 (dc-outer, 8 independent
// accumulator chains), w=exp(S) -> g_w, Z accumulated. Pass 2: reload w,
// threshold vs exact fp32 Z/T, PV tf32, scale 1/Z.
// Block = (bh, 128 q-rows), 256 threads, key tile 64, occ 2.
// ---------------------------------------------------------------------------
__global__ __launch_bounds__(256, 2) void attn_kernel()
{
    extern __shared__ uint32_t sma[];
    uint32_t* Kh  = sma;                  // [64][68]
    uint32_t* Kl  = Kh + 64 * 68;         // [64][68]
    uint32_t* Qlo = sma + 128 * 68;       // [128][68], persists through pass 1
    uint32_t* Qhi = sma;                  // [128][68] staging (over Kh+Kl)
    uint32_t* Ps  = sma;                  // pass2 [128][68] (over Kh+Kl)
    uint32_t* Vs  = sma + 128 * 68;       // pass2 [64][68]  (over Qlo)
    float*  thr_s = (float*)(sma + 256 * 68);   // [128]

    const int bh = blockIdx.x;
    const int q0 = blockIdx.y * 128;
    const float* qh = g_qh + (size_t)bh * T_ * DK_;
    const float* kh = g_kh + (size_t)bh * T_ * DK_;
    const float* vh = g_vh + (size_t)bh * T_ * DK_;
    float* wb = g_w + (size_t)bh * T_ * T_;
    float* oh = g_oh + (size_t)bh * T_ * DK_;

    const int tid  = threadIdx.x;
    const int lane = tid & 31, w = tid >> 5;
    const int g = lane >> 2, t4 = lane & 3;

    // ---- stage Q tile: hi -> Qhi scratch, lo -> Qlo (persistent) ----
    #pragma unroll
    for (int e = 0; e < 8; e++) {
        int idx = e * 256 + tid;
        int r = idx >> 4, c4 = (idx & 15) * 4;
        float4 qv = *(const float4*)&qh[(size_t)(q0 + r) * DK_ + c4];
        uint4 h, l;
        split3(qv.x, h.x, l.x); split3(qv.y, h.y, l.y);
        split3(qv.z, h.z, l.z); split3(qv.w, h.w, l.w);
        *(uint4*)&Qhi[r * 68 + c4] = h;
        *(uint4*)&Qlo[r * 68 + c4] = l;
    }
    __syncthreads();
    const int r0q = (16 * w + g) * 68, r1q = r0q + 8 * 68;
    uint32_t qh_[8][4];
    #pragma unroll
    for (int dc = 0; dc < 8; dc++) {
        qh_[dc][0] = Qhi[r0q + dc * 8 + t4];
        qh_[dc][1] = Qhi[r1q + dc * 8 + t4];
        qh_[dc][2] = Qhi[r0q + dc * 8 + t4 + 4];
        qh_[dc][3] = Qhi[r1q + dc * 8 + t4 + 4];
    }

    // ---- pass 1: S in 3xTF32, stream w=exp(S) to g_w, accumulate Z ----
    float z0 = 0.f, z1 = 0.f;
    float* wrA = wb + (size_t)(q0 + 16 * w + g) * T_;
    float* wrB = wrA + 8 * T_;
    for (int kt = 0; kt < T_ / 64; kt++) {
        const int j0 = kt * 64;
        __syncthreads();   // q-frag reads / prior c-loop done before K overwrite
        #pragma unroll
        for (int e = 0; e < 4; e++) {
            int idx = e * 256 + tid;
            int r = idx >> 4, c4 = (idx & 15) * 4;
            float4 kv = *(const float4*)&kh[(size_t)(j0 + r) * DK_ + c4];
            uint4 h, l;
            split3(kv.x, h.x, l.x); split3(kv.y, h.y, l.y);
            split3(kv.z, h.z, l.z); split3(kv.w, h.w, l.w);
            *(uint4*)&Kh[r * 68 + c4] = h;
            *(uint4*)&Kl[r * 68 + c4] = l;
        }
        __syncthreads();

        float c[8][4];
        #pragma unroll
        for (int i = 0; i < 8; i++)
            #pragma unroll
            for (int j = 0; j < 4; j++) c[i][j] = 0.f;

        // dc outer: per dc, 3 kc-sweeps (hh, hl, lh). Into each c[kc] the
        // order is hh,hl,lh per dc, dc ascending — identical to R5 math.
        #pragma unroll
        for (int dc = 0; dc < 8; dc++) {
            uint32_t qlo[4];
            qlo[0] = Qlo[r0q + dc * 8 + t4];
            qlo[1] = Qlo[r1q + dc * 8 + t4];
            qlo[2] = Qlo[r0q + dc * 8 + t4 + 4];
            qlo[3] = Qlo[r1q + dc * 8 + t4 + 4];
            uint32_t bh0[8], bh1[8];
            #pragma unroll
            for (int kc = 0; kc < 8; kc++) {
                const int br = (kc * 8 + g) * 68 + dc * 8;
                bh0[kc] = Kh[br + t4];
                bh1[kc] = Kh[br + t4 + 4];
                mma8(c[kc], qh_[dc], bh0[kc], bh1[kc]);     // hi*hi
            }
            #pragma unroll
            for (int kc = 0; kc < 8; kc++) {
                const int br = (kc * 8 + g) * 68 + dc * 8;
                uint32_t bl0 = Kl[br + t4];
                uint32_t bl1 = Kl[br + t4 + 4];
                mma8(c[kc], qh_[dc], bl0, bl1);             // hi*lo
            }
            #pragma unroll
            for (int kc = 0; kc < 8; kc++)
                mma8(c[kc], qlo, bh0[kc], bh1[kc]);         // lo*hi
        }

        #pragma unroll
        for (int kc = 0; kc < 8; kc++) {
            float w0 = __expf(c[kc][0]);
            float w1 = __expf(c[kc][1]);
            float w2 = __expf(c[kc][2]);
            float w3 = __expf(c[kc][3]);
            z0 += w0 + w1;
            z1 += w2 + w3;
            const int col = j0 + kc * 8 + 2 * t4;
            *(float2*)&wrA[col] = make_float2(w0, w1);
            *(float2*)&wrB[col] = make_float2(w2, w3);
        }
    }
    z0 += __shfl_xor_sync(0xffffffffu, z0, 1);
    z0 += __shfl_xor_sync(0xffffffffu, z0, 2);
    z1 += __shfl_xor_sync(0xffffffffu, z1, 1);
    z1 += __shfl_xor_sync(0xffffffffu, z1, 2);
    const float inv0 = 1.0f / z0, inv1 = 1.0f / z1;
    if (t4 == 0) {
        thr_s[16 * w + g]     = z0 * (1.0f / (float)T_);
        thr_s[16 * w + g + 8] = z1 * (1.0f / (float)T_);
    }

    // ---- pass 2: reload w, threshold (exact fp32), PV ----
    float o[8][4];
    #pragma unroll
    for (int i = 0; i < 8; i++)
        #pragma unroll
        for (int j = 0; j < 4; j++) o[i][j] = 0.f;

    const int r0p = (16 * w + g) * 68, r1p = r0p + 8 * 68;
    for (int kt = 0; kt < T_ / 64; kt++) {
        const int j0 = kt * 64;
        __syncthreads();   // orders thr_s writes (first iter) + Ps/Vs reuse
        #pragma unroll
        for (int e = 0; e < 8; e++) {              // P tile 128x64: load, thresh, cvt
            int idx = e * 256 + tid;
            int r = idx >> 4, j4 = (idx & 15) * 4;
            float4 w4 = *(const float4*)&wb[(size_t)(q0 + r) * T_ + j0 + j4];
            float th = thr_s[r];
            uint4 p;
            p.x = f2tf(w4.x > th ? w4.x : 0.f);
            p.y = f2tf(w4.y > th ? w4.y : 0.f);
            p.z = f2tf(w4.z > th ? w4.z : 0.f);
            p.w = f2tf(w4.w > th ? w4.w : 0.f);
            *(uint4*)&Ps[r * 68 + j4] = p;
        }
        #pragma unroll
        for (int e = 0; e < 4; e++) {              // V tile 64x64
            int idx = e * 256 + tid;
            int r = idx >> 4, d4 = (idx & 15) * 4;
            float4 vv = *(const float4*)&vh[(size_t)(j0 + r) * DK_ + d4];
            *(uint4*)&Vs[r * 68 + d4] = f2tf4(vv);
        }
        __syncthreads();
        #pragma unroll
        for (int kc = 0; kc < 8; kc++) {
            uint32_t pa[4];
            pa[0] = Ps[r0p + kc * 8 + t4];
            pa[1] = Ps[r1p + kc * 8 + t4];
            pa[2] = Ps[r0p + kc * 8 + t4 + 4];
            pa[3] = Ps[r1p + kc * 8 + t4 + 4];
            const int vr0 = (kc * 8 + t4) * 68;
            const int vr1 = vr0 + 4 * 68;
            #pragma unroll
            for (int dn = 0; dn < 8; dn++) {
                uint32_t b0 = Vs[vr0 + dn * 8 + g];
                uint32_t b1 = Vs[vr1 + dn * 8 + g];
                mma8(o[dn], pa, b0, b1);
            }
        }
    }

    float* rowA = oh + (size_t)(q0 + 16 * w + g) * DK_;
    float* rowB = rowA + 8 * DK_;
    #pragma unroll
    for (int dn = 0; dn < 8; dn++) {
        int col = dn * 8 + 2 * t4;
        *(float2*)&rowA[col] = make_float2(o[dn][0] * inv0, o[dn][1] * inv0);
        *(float2*)&rowB[col] = make_float2(o[dn][2] * inv1, o[dn][3] * inv1);
    }
}

// ---------------------------------------------------------------------------
// Kernel 3: output projection (single tf32). kc-outer for ILP.
// ---------------------------------------------------------------------------
__global__ __launch_bounds__(256, 2) void outproj_kernel(
    const float* __restrict__ Wo, const float* __restrict__ bo,
    float* __restrict__ out)
{
    __shared__ uint32_t Xs[128 * 36];
    __shared__ uint32_t Ws[64 * 36];

    const int tid  = threadIdx.x;
    const int lane = tid & 31, w = tid >> 5;
    const int g = lane >> 2, t4 = lane & 3;
    const int m0 = blockIdx.y * 128;
    const int n0 = blockIdx.x * 64;

    float acc[8][4];
    #pragma unroll
    for (int i = 0; i < 8; i++)
        #pragma unroll
        for (int j = 0; j < 4; j++) acc[i][j] = 0.f;

    for (int k0 = 0; k0 < DOUT_; k0 += 32) {
        __syncthreads();
        #pragma unroll
        for (int e = 0; e < 4; e++) {
            int idx = e * 256 + tid;
            int r = idx >> 3, c4 = (idx & 7) * 4;
            int m = m0 + r, bb = m >> 11, t = m & (T_ - 1);
            int kg = k0 + c4, h = kg >> 6, dk = kg & 63;
            float4 xv = *(const float4*)&g_oh[((size_t)(bb * H_ + h) * T_ + t) * DK_ + dk];
            *(uint4*)&Xs[r * 36 + c4] = f2tf4(xv);
        }
        #pragma unroll
        for (int e = 0; e < 2; e++) {
            int idx = e * 256 + tid;
            int r = idx >> 3, c4 = (idx & 7) * 4;
            float4 wv = *(const float4*)&Wo[(size_t)(n0 + r) * DOUT_ + k0 + c4];
            *(uint4*)&Ws[r * 36 + c4] = f2tf4(wv);
        }
        __syncthreads();

        uint32_t a[4][4];
        const int r0 = (16 * w + g) * 36, r1 = r0 + 8 * 36;
        #pragma unroll
        for (int kc = 0; kc < 4; kc++) {
            a[kc][0] = Xs[r0 + kc * 8 + t4];
            a[kc][1] = Xs[r1 + kc * 8 + t4];
            a[kc][2] = Xs[r0 + kc * 8 + t4 + 4];
            a[kc][3] = Xs[r1 + kc * 8 + t4 + 4];
        }
        #pragma unroll
        for (int kc = 0; kc < 4; kc++) {
            #pragma unroll
            for (int nc = 0; nc < 8; nc++) {
                const int br = (nc * 8 + g) * 36 + kc * 8;
                uint32_t b0 = Ws[br + t4];
                uint32_t b1 = Ws[br + t4 + 4];
                mma8(acc[nc], a[kc], b0, b1);
            }
        }
    }

    const int mA = m0 + 16 * w + g;
    float* rowA = out + (size_t)mA * DIN_ + n0;
    float* rowB = rowA + 8 * DIN_;
    #pragma unroll
    for (int nc = 0; nc < 8; nc++) {
        int col = nc * 8 + 2 * t4;
        float bx = bo[n0 + col], by = bo[n0 + col + 1];
        *(float2*)&rowA[col] = make_float2(acc[nc][0] + bx, acc[nc][1] + by);
        *(float2*)&rowB[col] = make_float2(acc[nc][2] + bx, acc[nc][3] + by);
    }
}

// ---------------------------------------------------------------------------
extern "C" void kernel_launch(void* const* d_in, const int* in_sizes, int n_in,
                              void* d_out, int out_size)
{
    const float* q  = (const float*)d_in[0];
    const float* k  = (const float*)d_in[1];
    const float* v  = (const float*)d_in[2];
    const float* Wq = (const float*)d_in[3];
    const float* bq = (const float*)d_in[4];
    const float* Wk = (const float*)d_in[5];
    const float* bk = (const float*)d_in[6];
    const float* Wv = (const float*)d_in[7];
    const float* bv = (const float*)d_in[8];
    const float* Wo = (const float*)d_in[9];
    const float* bo = (const float*)d_in[10];
    float* out = (float*)d_out;

    cudaFuncSetAttribute(proj_kernel,
        cudaFuncAttributeMaxDynamicSharedMemorySize, PROJ_SMEM_BYTES);
    cudaFuncSetAttribute(attn_kernel,
        cudaFuncAttributeMaxDynamicSharedMemorySize, ATTN_SMEM_BYTES);

    proj_kernel<<<dim3(DOUT_ / 64, (B_ * T_) / 128, 3), 256, PROJ_SMEM_BYTES>>>(
        q, k, v, Wq, bq, Wk, bk, Wv, bv);

    attn_kernel<<<dim3(BH_, T_ / 128), 256, ATTN_SMEM_BYTES>>>();

    outproj_kernel<<<dim3(DIN_ / 64, (B_ * T_) / 128), 256>>>(Wo, bo, out);
}